// round 10
// baseline (speedup 1.0000x reference)
#include <cuda_runtime.h>
#include <cuda_bf16.h>
#include <cstdint>

// ---------------------------------------------------------------------------
// VQ-EMA layer, GB300 (sm_103a) — round 9
// bf16 mma.sync m16n8k16 filter + exact fp32 recheck (bit-identical argmin).
// ---------------------------------------------------------------------------

constexpr int Dc = 256, Kc = 1024, Nrows = 16384, TM = 128;
constexpr float DECAYF = 0.99f, OMDF = 0.01f, EPSF = 1e-5f, KEPSF = 0.01024f;
constexpr float THETA = 8e-3f;     // > 3x hard |bf16 score - exact score| bound
constexpr int CAP = 32;

// ----- smem byte offsets (vq_main) -----
constexpr int SB_XP   = 0;                 // packed A tile (bf16 frags): 64KB
constexpr int SB_WSQ  = 65536;             // 1024 f32 = 4KB
constexpr int SB_RMIN = 69632;             // 128 u32
constexpr int SB_CNT  = 70144;             // 128 i32
constexpr int SB_LIST = 70656;             // 128 x 32 i32 = 16KB
constexpr int SB_FIN  = 87040;             // 128 i32
constexpr int SB_RED  = 87552;             // 8 f32
constexpr int SMEM_MAIN = 87808;

// ----- device scratch (no allocations allowed) -----
__device__ float g_xsq[Nrows];
__device__ float g_wsq[Kc];
__device__ uint2 g_wpb[65536];      // bf16 B fragments: ((nblk*16+k16)*32+lane) -> {b0,b1}
__device__ float g_dw[Kc * Dc];
__device__ float g_counts[Kc];
__device__ float g_loss;

__device__ __forceinline__ uint32_t encf(float x) {
  uint32_t u = __float_as_uint(x);
  return (u & 0x80000000u) ? ~u : (u | 0x80000000u);
}
__device__ __forceinline__ float decf(uint32_t e) {
  return (e & 0x80000000u) ? __uint_as_float(e ^ 0x80000000u) : __uint_as_float(~e);
}
__device__ __forceinline__ uint32_t pkbf(float a, float b) {
  __nv_bfloat162 h = __floats2bfloat162_rn(a, b);   // .x = a (low 16), .y = b
  return *reinterpret_cast<uint32_t*>(&h);
}

// ---------------------------------------------------------------------------
// Kernel 0: xsq/wsq (reduction BYTE-IDENTICAL to all passing rounds);
// build bf16 fragment-packed w; zero scatter scratch.
// ---------------------------------------------------------------------------
__global__ void prep_kernel(const float* __restrict__ x, const float* __restrict__ w) {
  int b = blockIdx.x, t = threadIdx.x;
  float v;
  if (b < Nrows) {
    v = x[(size_t)b * Dc + t];
  } else {
    int k = b - Nrows;
    v = w[(size_t)k * Dc + t];
    // B fragment pos: nblk=k>>3, gid=k&7; k16=t>>4; rem=t&15: tg=(rem&7)>>1,
    // part=rem>>3, lo=rem&1. u16 index = e*4 + part*2 + lo.
    int rem = t & 15;
    size_t e = ((size_t)(k >> 3) * 16 + (t >> 4)) * 32 + (k & 7) * 4 + ((rem & 7) >> 1);
    __nv_bfloat16 hb = __float2bfloat16_rn(v);
    reinterpret_cast<__nv_bfloat16*>(g_wpb)[e * 4 + (rem >> 3) * 2 + (rem & 1)] = hb;
    g_dw[(size_t)k * Dc + t] = 0.0f;
    if (t == 0) g_counts[k] = 0.0f;
    if (t == 1 && k == 0) g_loss = 0.0f;
  }
  float s = v * v;
  #pragma unroll
  for (int o = 16; o; o >>= 1) s += __shfl_down_sync(0xffffffffu, s, o);
  __shared__ float red[8];
  if ((t & 31) == 0) red[t >> 5] = s;
  __syncthreads();
  if (t == 0) {
    float tot = red[0];
    #pragma unroll
    for (int i = 1; i < 8; i++) tot += red[i];
    if (b < Nrows) g_xsq[b] = tot;
    else           g_wsq[b - Nrows] = tot;
  }
}

// ---------------------------------------------------------------------------
// Kernel 1: bf16 mma.sync GEMM filter + exact recheck + epilogue.
// 128 CTAs x 256 threads (8 warps: 2 row-halves x 4 col-groups).
// Warp tile: m64 x n64 per chunk, 4 chunks of 64 cols, K=256 (16 k16 steps).
// ---------------------------------------------------------------------------
__global__ void __launch_bounds__(256, 1)
vq_main(const float* __restrict__ x, const float* __restrict__ w,
        float* __restrict__ outQ) {
  extern __shared__ char smem[];
  uint4* sA4 = reinterpret_cast<uint4*>(smem + SB_XP);       // 4096 uint4
  float*  sWsq = reinterpret_cast<float*>(smem + SB_WSQ);
  uint32_t* sRmin = reinterpret_cast<uint32_t*>(smem + SB_RMIN);
  int* sCnt  = reinterpret_cast<int*>(smem + SB_CNT);
  int* sList = reinterpret_cast<int*>(smem + SB_LIST);
  int* sFin  = reinterpret_cast<int*>(smem + SB_FIN);
  float* sRed = reinterpret_cast<float*>(smem + SB_RED);

  const int tid = threadIdx.x;
  const int lane = tid & 31;
  const int wid = tid >> 5;
  const int gid = lane >> 2;       // 0..7
  const int tg  = lane & 3;        // 0..3
  const int rh = wid & 1;          // row half (64 rows)
  const int cg = wid >> 1;         // col group (256 cols)
  const int rowBase = blockIdx.x * TM;

  if (tid < 128) { sRmin[tid] = 0xFFFFFFFFu; sCnt[tid] = 0; }
  #pragma unroll
  for (int i = 0; i < 4; i++) sWsq[tid + 256 * i] = g_wsq[tid + 256 * i];

  // ---- pack A (x -> bf16 fragments): uint4 at ((mblk*16+k16)*32 + lane) =
  //   { pk(x[r][c],x[r][c+1]), pk(x[r+8][c],..), pk(x[r][c+8],..), pk(x[r+8][c+8],..) }
  //   r = mblk*16+gid, c = k16*16+2*tg.
  {
    #pragma unroll
    for (int i = 0; i < 16; i++) {
      int pidx = tid + 256 * i;
      int blk = pidx >> 5;                 // mblk*16 + k16
      int k16 = blk & 15, mblk = blk >> 4;
      int r = mblk * 16 + gid;
      int c0 = k16 * 16 + 2 * tg;
      const float* xb = x + (size_t)(rowBase + r) * Dc + c0;
      float2 v00 = *reinterpret_cast<const float2*>(xb);
      float2 v10 = *reinterpret_cast<const float2*>(xb + 8 * Dc);
      float2 v01 = *reinterpret_cast<const float2*>(xb + 8);
      float2 v11 = *reinterpret_cast<const float2*>(xb + 8 * Dc + 8);
      uint4 o;
      o.x = pkbf(v00.x, v00.y);
      o.y = pkbf(v10.x, v10.y);
      o.z = pkbf(v01.x, v01.y);
      o.w = pkbf(v11.x, v11.y);
      sA4[pidx] = o;
    }
  }
  __syncthreads();

  // ---- GEMM filter: 4 chunks of 64 cols per warp
  for (int ch = 0; ch < 4; ch++) {
    const int cb = cg * 256 + ch * 64;
    const uint2* bbase = g_wpb + (size_t)(cb >> 3) * 512 + lane;

    float c[4][8][4];
    #pragma unroll
    for (int i = 0; i < 4; i++)
      #pragma unroll
      for (int j = 0; j < 8; j++)
        c[i][j][0] = c[i][j][1] = c[i][j][2] = c[i][j][3] = 0.0f;

    #pragma unroll
    for (int k16 = 0; k16 < 16; k16++) {
      uint4 a[4];
      #pragma unroll
      for (int m = 0; m < 4; m++)
        a[m] = sA4[((rh * 4 + m) * 16 + k16) * 32 + lane];
      uint2 bv[8];
      #pragma unroll
      for (int nt = 0; nt < 8; nt++)
        bv[nt] = bbase[nt * 512 + k16 * 32];
      #pragma unroll
      for (int m = 0; m < 4; m++) {
        #pragma unroll
        for (int nt = 0; nt < 8; nt++) {
          asm volatile(
            "mma.sync.aligned.m16n8k16.row.col.f32.bf16.bf16.f32 "
            "{%0,%1,%2,%3},{%4,%5,%6,%7},{%8,%9},{%0,%1,%2,%3};"
            : "+f"(c[m][nt][0]), "+f"(c[m][nt][1]), "+f"(c[m][nt][2]), "+f"(c[m][nt][3])
            : "r"(a[m].x), "r"(a[m].y), "r"(a[m].z), "r"(a[m].w),
              "r"(bv[nt].x), "r"(bv[nt].y));
        }
      }
    }

    // ---- phase A: per-row shared running min (order-encoded atomicMin)
    #pragma unroll
    for (int m = 0; m < 4; m++) {
      float m0 = 3.4e38f, m1 = 3.4e38f;
      #pragma unroll
      for (int nt = 0; nt < 8; nt++) {
        int col0 = cb + nt * 8 + 2 * tg;
        float s0 = fmaf(-2.0f, c[m][nt][0], sWsq[col0]);
        float s1 = fmaf(-2.0f, c[m][nt][1], sWsq[col0 + 1]);
        float s2 = fmaf(-2.0f, c[m][nt][2], sWsq[col0]);
        float s3 = fmaf(-2.0f, c[m][nt][3], sWsq[col0 + 1]);
        m0 = fminf(m0, fminf(s0, s1));
        m1 = fminf(m1, fminf(s2, s3));
      }
      int r0 = (rh * 4 + m) * 16 + gid;
      atomicMin(&sRmin[r0], encf(m0));
      atomicMin(&sRmin[r0 + 8], encf(m1));
    }
    __syncthreads();

    // ---- phase B: collect candidates within THETA of (monotone) row min
    #pragma unroll
    for (int m = 0; m < 4; m++) {
      int r0 = (rh * 4 + m) * 16 + gid;
      float th0 = decf(sRmin[r0]) + THETA;
      float th1 = decf(sRmin[r0 + 8]) + THETA;
      #pragma unroll
      for (int nt = 0; nt < 8; nt++) {
        int col0 = cb + nt * 8 + 2 * tg;
        float s0 = fmaf(-2.0f, c[m][nt][0], sWsq[col0]);
        float s1 = fmaf(-2.0f, c[m][nt][1], sWsq[col0 + 1]);
        float s2 = fmaf(-2.0f, c[m][nt][2], sWsq[col0]);
        float s3 = fmaf(-2.0f, c[m][nt][3], sWsq[col0 + 1]);
        if (s0 < th0) { int p = atomicAdd(&sCnt[r0], 1);     if (p < CAP) sList[r0 * CAP + p] = col0; }
        if (s1 < th0) { int p = atomicAdd(&sCnt[r0], 1);     if (p < CAP) sList[r0 * CAP + p] = col0 + 1; }
        if (s2 < th1) { int p = atomicAdd(&sCnt[r0 + 8], 1); if (p < CAP) sList[(r0 + 8) * CAP + p] = col0; }
        if (s3 < th1) { int p = atomicAdd(&sCnt[r0 + 8], 1); if (p < CAP) sList[(r0 + 8) * CAP + p] = col0 + 1; }
      }
    }
    __syncthreads();
  }

  // ---- exact recheck (threads 0-127, row = tid); bit-identical score chain
  if (tid < 128) {
    int nc = sCnt[tid];
    if (nc > CAP) nc = CAP;
    int kbest = Kc;
    if (nc == 1) {
      kbest = sList[tid * CAP];
    } else {
      float xsq = g_xsq[rowBase + tid];
      const float4* xr = reinterpret_cast<const float4*>(x + (size_t)(rowBase + tid) * Dc);
      float bs = 3.4e38f;
      for (int i = 0; i < nc; i++) {
        int k = sList[tid * CAP + i];
        const float4* wr = reinterpret_cast<const float4*>(w + (size_t)k * Dc);
        float acc = 0.0f;
        #pragma unroll 8
        for (int d4 = 0; d4 < 64; d4++) {
          float4 xv = xr[d4], wv = wr[d4];
          acc = fmaf(xv.x, wv.x, acc);
          acc = fmaf(xv.y, wv.y, acc);
          acc = fmaf(xv.z, wv.z, acc);
          acc = fmaf(xv.w, wv.w, acc);
        }
        float r1 = __fadd_rn(xsq, sWsq[k]);
        float s  = __fadd_rn(r1, -2.0f * acc);
        if (s < bs || (s == bs && k < kbest)) { bs = s; kbest = k; }
      }
    }
    sFin[tid] = kbest;
    atomicAdd(&g_counts[kbest], 1.0f);
  }
  __syncthreads();

  // ---- epilogue: gather quantized rows, loss partial, dw scatter
  float lsum = 0.0f;
  {
    int q = tid & 63, rg = tid >> 6;
    #pragma unroll 4
    for (int it = 0; it < 32; ++it) {
      int row = rg * 32 + it;
      int k = sFin[row];
      float4 wv = *reinterpret_cast<const float4*>(w + (size_t)k * Dc + 4 * q);
      float4 xv = *reinterpret_cast<const float4*>(x + (size_t)(rowBase + row) * Dc + 4 * q);
      *reinterpret_cast<float4*>(outQ + (size_t)(rowBase + row) * Dc + 4 * q) = wv;
      float d0 = xv.x - wv.x, d1 = xv.y - wv.y, d2 = xv.z - wv.z, d3 = xv.w - wv.w;
      lsum += d0 * d0 + d1 * d1 + d2 * d2 + d3 * d3;
      float* dwp = g_dw + (size_t)k * Dc + 4 * q;
      atomicAdd(dwp + 0, xv.x);
      atomicAdd(dwp + 1, xv.y);
      atomicAdd(dwp + 2, xv.z);
      atomicAdd(dwp + 3, xv.w);
    }
  }
  #pragma unroll
  for (int o = 16; o; o >>= 1) lsum += __shfl_down_sync(0xffffffffu, lsum, o);
  if ((tid & 31) == 0) sRed[tid >> 5] = lsum;
  __syncthreads();
  if (tid == 0) {
    float tot = sRed[0];
    #pragma unroll
    for (int i = 1; i < 8; i++) tot += sRed[i];
    atomicAdd(&g_loss, tot);
  }
}

// ---------------------------------------------------------------------------
// Kernel 2: cluster-size EMA + Laplace + ema_w EMA + embed (validated).
// ---------------------------------------------------------------------------
__global__ void emacs_kernel(const float* __restrict__ ema_cs,
                             const float* __restrict__ ema_w,
                             float* __restrict__ outLoss, float* __restrict__ outEmbed,
                             float* __restrict__ outCS, float* __restrict__ outEmaW) {
  int k = blockIdx.x, d = threadIdx.x;
  __shared__ float red[8];
  __shared__ float s_cs;
  float4 v = reinterpret_cast<const float4*>(ema_cs)[d];
  float s = v.x + v.y + v.z + v.w;
  #pragma unroll
  for (int o = 16; o; o >>= 1) s += __shfl_down_sync(0xffffffffu, s, o);
  if ((d & 31) == 0) red[d >> 5] = s;
  __syncthreads();
  if (d == 0) {
    float S = red[0];
    #pragma unroll
    for (int i = 1; i < 8; i++) S += red[i];
    float n = DECAYF * S + OMDF * (float)Nrows;
    float c = ema_cs[k] * DECAYF + OMDF * g_counts[k];
    float csf = (c + EPSF) / (n + KEPSF) * n;
    s_cs = csf;
    outCS[k] = csf;
    if (k == 0) outLoss[0] = 0.25f * g_loss * (1.0f / 4194304.0f);
  }
  __syncthreads();
  size_t i = (size_t)k * Dc + d;
  float ew = ema_w[i] * DECAYF + OMDF * g_dw[i];
  outEmaW[i]  = ew;
  outEmbed[i] = ew / s_cs;
}

// ---------------------------------------------------------------------------
extern "C" void kernel_launch(void* const* d_in, const int* in_sizes, int n_in,
                              void* d_out, int out_size) {
  const float* x      = (const float*)d_in[0];
  const float* w      = (const float*)d_in[1];
  const float* ema_cs = (const float*)d_in[2];
  const float* ema_w  = (const float*)d_in[3];

  float* out      = (float*)d_out;
  float* outQ     = out;
  float* outLoss  = out + (size_t)Nrows * Dc;
  float* outEmbed = outLoss + 1;
  float* outCS    = outEmbed + (size_t)Kc * Dc;
  float* outEmaW  = outCS + Kc;

  cudaFuncSetAttribute(vq_main, cudaFuncAttributeMaxDynamicSharedMemorySize, SMEM_MAIN);

  prep_kernel<<<Nrows + Kc, 256>>>(x, w);
  vq_main<<<Nrows / TM, 256, SMEM_MAIN>>>(x, w, outQ);
  emacs_kernel<<<Kc, 256>>>(ema_cs, ema_w, outLoss, outEmbed, outCS, outEmaW);
}

// round 11
// speedup vs baseline: 1.2494x; 1.2494x over previous
#include <cuda_runtime.h>
#include <cuda_bf16.h>
#include <cstdint>

// ---------------------------------------------------------------------------
// VQ-EMA layer, GB300 (sm_103a) — round 10
// bf16 mma.sync filter + exact fp32 recheck (parallelized) + vector-atomic dw.
// ---------------------------------------------------------------------------

constexpr int Dc = 256, Kc = 1024, Nrows = 16384, TM = 128;
constexpr float DECAYF = 0.99f, OMDF = 0.01f, EPSF = 1e-5f, KEPSF = 0.01024f;
constexpr float THETA = 8e-3f;     // > 3x hard |bf16 score - exact score| bound
constexpr int CAP = 32;

// ----- smem byte offsets (vq_main) -----
constexpr int SB_XP   = 0;                 // packed A tile (bf16 frags): 64KB
constexpr int SB_WSQ  = 65536;             // 1024 f32 = 4KB
constexpr int SB_RMIN = 69632;             // 128 u32
constexpr int SB_CNT  = 70144;             // 128 i32
constexpr int SB_LIST = 70656;             // 128 x 32 i32 = 16KB
constexpr int SB_FIN  = 87040;             // 128 i32
constexpr int SB_RED  = 87552;             // 8 f32 (+pad)
constexpr int SB_BEST = 87616;             // 128 u64 = 1KB
constexpr int SMEM_MAIN = 88640;

// ----- device scratch (no allocations allowed) -----
__device__ float g_xsq[Nrows];
__device__ float g_wsq[Kc];
__device__ uint2 g_wpb[65536];      // bf16 B fragments: ((nblk*16+k16)*32+lane) -> {b0,b1}
__device__ float g_dw[Kc * Dc];
__device__ float g_counts[Kc];
__device__ float g_loss;

__device__ __forceinline__ uint32_t encf(float x) {
  uint32_t u = __float_as_uint(x);
  return (u & 0x80000000u) ? ~u : (u | 0x80000000u);
}
__device__ __forceinline__ float decf(uint32_t e) {
  return (e & 0x80000000u) ? __uint_as_float(e ^ 0x80000000u) : __uint_as_float(~e);
}
__device__ __forceinline__ uint32_t pkbf(float a, float b) {
  __nv_bfloat162 h = __floats2bfloat162_rn(a, b);
  return *reinterpret_cast<uint32_t*>(&h);
}

// ---------------------------------------------------------------------------
// Kernel 0: xsq/wsq (reduction BYTE-IDENTICAL to all passing rounds);
// build bf16 fragment-packed w; zero scatter scratch.
// ---------------------------------------------------------------------------
__global__ void prep_kernel(const float* __restrict__ x, const float* __restrict__ w) {
  int b = blockIdx.x, t = threadIdx.x;
  float v;
  if (b < Nrows) {
    v = x[(size_t)b * Dc + t];
  } else {
    int k = b - Nrows;
    v = w[(size_t)k * Dc + t];
    int rem = t & 15;
    size_t e = ((size_t)(k >> 3) * 16 + (t >> 4)) * 32 + (k & 7) * 4 + ((rem & 7) >> 1);
    __nv_bfloat16 hb = __float2bfloat16_rn(v);
    reinterpret_cast<__nv_bfloat16*>(g_wpb)[e * 4 + (rem >> 3) * 2 + (rem & 1)] = hb;
    g_dw[(size_t)k * Dc + t] = 0.0f;
    if (t == 0) g_counts[k] = 0.0f;
    if (t == 1 && k == 0) g_loss = 0.0f;
  }
  float s = v * v;
  #pragma unroll
  for (int o = 16; o; o >>= 1) s += __shfl_down_sync(0xffffffffu, s, o);
  __shared__ float red[8];
  if ((t & 31) == 0) red[t >> 5] = s;
  __syncthreads();
  if (t == 0) {
    float tot = red[0];
    #pragma unroll
    for (int i = 1; i < 8; i++) tot += red[i];
    if (b < Nrows) g_xsq[b] = tot;
    else           g_wsq[b - Nrows] = tot;
  }
}

// ---------------------------------------------------------------------------
// Kernel 1: bf16 mma.sync GEMM filter + parallel exact recheck + epilogue.
// 128 CTAs x 256 threads (8 warps: 2 row-halves x 4 col-groups).
// ---------------------------------------------------------------------------
__global__ void __launch_bounds__(256, 1)
vq_main(const float* __restrict__ x, const float* __restrict__ w,
        float* __restrict__ outQ) {
  extern __shared__ char smem[];
  uint4* sA4 = reinterpret_cast<uint4*>(smem + SB_XP);
  float*  sWsq = reinterpret_cast<float*>(smem + SB_WSQ);
  uint32_t* sRmin = reinterpret_cast<uint32_t*>(smem + SB_RMIN);
  int* sCnt  = reinterpret_cast<int*>(smem + SB_CNT);
  int* sList = reinterpret_cast<int*>(smem + SB_LIST);
  int* sFin  = reinterpret_cast<int*>(smem + SB_FIN);
  float* sRed = reinterpret_cast<float*>(smem + SB_RED);
  unsigned long long* sBest = reinterpret_cast<unsigned long long*>(smem + SB_BEST);

  const int tid = threadIdx.x;
  const int lane = tid & 31;
  const int wid = tid >> 5;
  const int gid = lane >> 2;
  const int tg  = lane & 3;
  const int rh = wid & 1;
  const int cg = wid >> 1;
  const int rowBase = blockIdx.x * TM;

  if (tid < 128) {
    sRmin[tid] = 0xFFFFFFFFu;
    sCnt[tid] = 0;
    sBest[tid] = 0xFFFFFFFFFFFFFFFFull;
  }
  #pragma unroll
  for (int i = 0; i < 4; i++) sWsq[tid + 256 * i] = g_wsq[tid + 256 * i];

  // ---- pack A (x -> bf16 fragments)
  {
    #pragma unroll
    for (int i = 0; i < 16; i++) {
      int pidx = tid + 256 * i;
      int blk = pidx >> 5;
      int k16 = blk & 15, mblk = blk >> 4;
      int r = mblk * 16 + gid;
      int c0 = k16 * 16 + 2 * tg;
      const float* xb = x + (size_t)(rowBase + r) * Dc + c0;
      float2 v00 = *reinterpret_cast<const float2*>(xb);
      float2 v10 = *reinterpret_cast<const float2*>(xb + 8 * Dc);
      float2 v01 = *reinterpret_cast<const float2*>(xb + 8);
      float2 v11 = *reinterpret_cast<const float2*>(xb + 8 * Dc + 8);
      uint4 o;
      o.x = pkbf(v00.x, v00.y);
      o.y = pkbf(v10.x, v10.y);
      o.z = pkbf(v01.x, v01.y);
      o.w = pkbf(v11.x, v11.y);
      sA4[pidx] = o;
    }
  }
  __syncthreads();

  // ---- GEMM filter: 4 chunks of 64 cols per warp
  for (int ch = 0; ch < 4; ch++) {
    const int cb = cg * 256 + ch * 64;
    const uint2* bbase = g_wpb + (size_t)(cb >> 3) * 512 + lane;

    float c[4][8][4];
    #pragma unroll
    for (int i = 0; i < 4; i++)
      #pragma unroll
      for (int j = 0; j < 8; j++)
        c[i][j][0] = c[i][j][1] = c[i][j][2] = c[i][j][3] = 0.0f;

    uint2 bv[8], bn[8];
    #pragma unroll
    for (int nt = 0; nt < 8; nt++) bv[nt] = bbase[nt * 512];

    #pragma unroll
    for (int k16 = 0; k16 < 16; k16++) {
      if (k16 < 15) {
        #pragma unroll
        for (int nt = 0; nt < 8; nt++) bn[nt] = bbase[nt * 512 + (k16 + 1) * 32];
      }
      uint4 a[4];
      #pragma unroll
      for (int m = 0; m < 4; m++)
        a[m] = sA4[((rh * 4 + m) * 16 + k16) * 32 + lane];
      #pragma unroll
      for (int m = 0; m < 4; m++) {
        #pragma unroll
        for (int nt = 0; nt < 8; nt++) {
          asm volatile(
            "mma.sync.aligned.m16n8k16.row.col.f32.bf16.bf16.f32 "
            "{%0,%1,%2,%3},{%4,%5,%6,%7},{%8,%9},{%0,%1,%2,%3};"
            : "+f"(c[m][nt][0]), "+f"(c[m][nt][1]), "+f"(c[m][nt][2]), "+f"(c[m][nt][3])
            : "r"(a[m].x), "r"(a[m].y), "r"(a[m].z), "r"(a[m].w),
              "r"(bv[nt].x), "r"(bv[nt].y));
        }
      }
      #pragma unroll
      for (int nt = 0; nt < 8; nt++) bv[nt] = bn[nt];
    }

    // ---- phase A: per-row min; quad shfl-reduce then one atomicMin per quad
    #pragma unroll
    for (int m = 0; m < 4; m++) {
      float m0 = 3.4e38f, m1 = 3.4e38f;
      #pragma unroll
      for (int nt = 0; nt < 8; nt++) {
        int col0 = cb + nt * 8 + 2 * tg;
        float s0 = fmaf(-2.0f, c[m][nt][0], sWsq[col0]);
        float s1 = fmaf(-2.0f, c[m][nt][1], sWsq[col0 + 1]);
        float s2 = fmaf(-2.0f, c[m][nt][2], sWsq[col0]);
        float s3 = fmaf(-2.0f, c[m][nt][3], sWsq[col0 + 1]);
        m0 = fminf(m0, fminf(s0, s1));
        m1 = fminf(m1, fminf(s2, s3));
      }
      m0 = fminf(m0, __shfl_xor_sync(0xffffffffu, m0, 1));
      m0 = fminf(m0, __shfl_xor_sync(0xffffffffu, m0, 2));
      m1 = fminf(m1, __shfl_xor_sync(0xffffffffu, m1, 1));
      m1 = fminf(m1, __shfl_xor_sync(0xffffffffu, m1, 2));
      int r0 = (rh * 4 + m) * 16 + gid;
      if (tg == 0) {
        atomicMin(&sRmin[r0], encf(m0));
        atomicMin(&sRmin[r0 + 8], encf(m1));
      }
    }
    __syncthreads();

    // ---- phase B: collect candidates within THETA of (monotone) row min
    #pragma unroll
    for (int m = 0; m < 4; m++) {
      int r0 = (rh * 4 + m) * 16 + gid;
      float th0 = decf(sRmin[r0]) + THETA;
      float th1 = decf(sRmin[r0 + 8]) + THETA;
      #pragma unroll
      for (int nt = 0; nt < 8; nt++) {
        int col0 = cb + nt * 8 + 2 * tg;
        float s0 = fmaf(-2.0f, c[m][nt][0], sWsq[col0]);
        float s1 = fmaf(-2.0f, c[m][nt][1], sWsq[col0 + 1]);
        float s2 = fmaf(-2.0f, c[m][nt][2], sWsq[col0]);
        float s3 = fmaf(-2.0f, c[m][nt][3], sWsq[col0 + 1]);
        if (s0 < th0) { int p = atomicAdd(&sCnt[r0], 1);     if (p < CAP) sList[r0 * CAP + p] = col0; }
        if (s1 < th0) { int p = atomicAdd(&sCnt[r0], 1);     if (p < CAP) sList[r0 * CAP + p] = col0 + 1; }
        if (s2 < th1) { int p = atomicAdd(&sCnt[r0 + 8], 1); if (p < CAP) sList[(r0 + 8) * CAP + p] = col0; }
        if (s3 < th1) { int p = atomicAdd(&sCnt[r0 + 8], 1); if (p < CAP) sList[(r0 + 8) * CAP + p] = col0 + 1; }
      }
    }
    __syncthreads();
  }

  // ---- exact recheck: 2 threads per row, 4-wide independent chains.
  // Per-candidate chain bit-identical to all passing rounds; combine via
  // lexicographic (encf(score), k) u64 min == (score, lowest-k) rule.
  {
    int row = tid & 127;
    int h = tid >> 7;
    int nc = sCnt[row]; if (nc > CAP) nc = CAP;
    if (nc == 1) {
      if (h == 0) sBest[row] = (unsigned long long)(uint32_t)sList[row * CAP];
    } else {
      int mc = (nc - h + 1) >> 1;     // this thread's candidates: h, h+2, ...
      if (mc > 0) {
        float xsq = g_xsq[rowBase + row];
        const float4* xr = reinterpret_cast<const float4*>(x + (size_t)(rowBase + row) * Dc);
        float bs = 3.4e38f; int kb = Kc;
        for (int b = 0; b < mc; b += 4) {
          int kk[4];
          #pragma unroll
          for (int j = 0; j < 4; j++) {
            int idx = b + j;
            kk[j] = sList[row * CAP + h + 2 * ((idx < mc) ? idx : b)];
          }
          const float4* w0 = reinterpret_cast<const float4*>(w + (size_t)kk[0] * Dc);
          const float4* w1 = reinterpret_cast<const float4*>(w + (size_t)kk[1] * Dc);
          const float4* w2 = reinterpret_cast<const float4*>(w + (size_t)kk[2] * Dc);
          const float4* w3 = reinterpret_cast<const float4*>(w + (size_t)kk[3] * Dc);
          float a0 = 0.f, a1 = 0.f, a2 = 0.f, a3 = 0.f;
          #pragma unroll 4
          for (int d4 = 0; d4 < 64; d4++) {
            float4 xv = xr[d4];
            float4 v0 = w0[d4], v1 = w1[d4], v2 = w2[d4], v3 = w3[d4];
            a0 = fmaf(xv.x, v0.x, a0); a0 = fmaf(xv.y, v0.y, a0);
            a0 = fmaf(xv.z, v0.z, a0); a0 = fmaf(xv.w, v0.w, a0);
            a1 = fmaf(xv.x, v1.x, a1); a1 = fmaf(xv.y, v1.y, a1);
            a1 = fmaf(xv.z, v1.z, a1); a1 = fmaf(xv.w, v1.w, a1);
            a2 = fmaf(xv.x, v2.x, a2); a2 = fmaf(xv.y, v2.y, a2);
            a2 = fmaf(xv.z, v2.z, a2); a2 = fmaf(xv.w, v2.w, a2);
            a3 = fmaf(xv.x, v3.x, a3); a3 = fmaf(xv.y, v3.y, a3);
            a3 = fmaf(xv.z, v3.z, a3); a3 = fmaf(xv.w, v3.w, a3);
          }
          float ac[4] = {a0, a1, a2, a3};
          #pragma unroll
          for (int j = 0; j < 4; j++) {
            if (b + j < mc) {
              float r1 = __fadd_rn(xsq, sWsq[kk[j]]);
              float s  = __fadd_rn(r1, -2.0f * ac[j]);
              if (s < bs || (s == bs && kk[j] < kb)) { bs = s; kb = kk[j]; }
            }
          }
        }
        atomicMin(&sBest[row], ((unsigned long long)encf(bs) << 32) | (uint32_t)kb);
      }
    }
  }
  __syncthreads();
  if (tid < 128) {
    int kbest = (int)(sBest[tid] & 0xFFFFFFFFull);
    sFin[tid] = kbest;
    atomicAdd(&g_counts[kbest], 1.0f);
  }
  __syncthreads();

  // ---- epilogue: gather quantized rows, loss partial, dw scatter (vec atomics)
  float lsum = 0.0f;
  {
    int q = tid & 63, rg = tid >> 6;
    #pragma unroll 4
    for (int it = 0; it < 32; ++it) {
      int row = rg * 32 + it;
      int k = sFin[row];
      float4 wv = *reinterpret_cast<const float4*>(w + (size_t)k * Dc + 4 * q);
      float4 xv = *reinterpret_cast<const float4*>(x + (size_t)(rowBase + row) * Dc + 4 * q);
      *reinterpret_cast<float4*>(outQ + (size_t)(rowBase + row) * Dc + 4 * q) = wv;
      float d0 = xv.x - wv.x, d1 = xv.y - wv.y, d2 = xv.z - wv.z, d3 = xv.w - wv.w;
      lsum += d0 * d0 + d1 * d1 + d2 * d2 + d3 * d3;
      atomicAdd(reinterpret_cast<float4*>(g_dw + (size_t)k * Dc + 4 * q), xv);
    }
  }
  #pragma unroll
  for (int o = 16; o; o >>= 1) lsum += __shfl_down_sync(0xffffffffu, lsum, o);
  if ((tid & 31) == 0) sRed[tid >> 5] = lsum;
  __syncthreads();
  if (tid == 0) {
    float tot = sRed[0];
    #pragma unroll
    for (int i = 1; i < 8; i++) tot += sRed[i];
    atomicAdd(&g_loss, tot);
  }
}

// ---------------------------------------------------------------------------
// Kernel 2: cluster-size EMA + Laplace + ema_w EMA + embed (validated).
// ---------------------------------------------------------------------------
__global__ void emacs_kernel(const float* __restrict__ ema_cs,
                             const float* __restrict__ ema_w,
                             float* __restrict__ outLoss, float* __restrict__ outEmbed,
                             float* __restrict__ outCS, float* __restrict__ outEmaW) {
  int k = blockIdx.x, d = threadIdx.x;
  __shared__ float red[8];
  __shared__ float s_cs;
  float4 v = reinterpret_cast<const float4*>(ema_cs)[d];
  float s = v.x + v.y + v.z + v.w;
  #pragma unroll
  for (int o = 16; o; o >>= 1) s += __shfl_down_sync(0xffffffffu, s, o);
  if ((d & 31) == 0) red[d >> 5] = s;
  __syncthreads();
  if (d == 0) {
    float S = red[0];
    #pragma unroll
    for (int i = 1; i < 8; i++) S += red[i];
    float n = DECAYF * S + OMDF * (float)Nrows;
    float c = ema_cs[k] * DECAYF + OMDF * g_counts[k];
    float csf = (c + EPSF) / (n + KEPSF) * n;
    s_cs = csf;
    outCS[k] = csf;
    if (k == 0) outLoss[0] = 0.25f * g_loss * (1.0f / 4194304.0f);
  }
  __syncthreads();
  size_t i = (size_t)k * Dc + d;
  float ew = ema_w[i] * DECAYF + OMDF * g_dw[i];
  outEmaW[i]  = ew;
  outEmbed[i] = ew / s_cs;
}

// ---------------------------------------------------------------------------
extern "C" void kernel_launch(void* const* d_in, const int* in_sizes, int n_in,
                              void* d_out, int out_size) {
  const float* x      = (const float*)d_in[0];
  const float* w      = (const float*)d_in[1];
  const float* ema_cs = (const float*)d_in[2];
  const float* ema_w  = (const float*)d_in[3];

  float* out      = (float*)d_out;
  float* outQ     = out;
  float* outLoss  = out + (size_t)Nrows * Dc;
  float* outEmbed = outLoss + 1;
  float* outCS    = outEmbed + (size_t)Kc * Dc;
  float* outEmaW  = outCS + Kc;

  cudaFuncSetAttribute(vq_main, cudaFuncAttributeMaxDynamicSharedMemorySize, SMEM_MAIN);

  prep_kernel<<<Nrows + Kc, 256>>>(x, w);
  vq_main<<<Nrows / TM, 256, SMEM_MAIN>>>(x, w, outQ);
  emacs_kernel<<<Kc, 256>>>(ema_cs, ema_w, outLoss, outEmbed, outCS, outEmaW);
}

// round 12
// speedup vs baseline: 1.2955x; 1.0368x over previous
#include <cuda_runtime.h>
#include <cuda_bf16.h>
#include <cstdint>

// ---------------------------------------------------------------------------
// VQ-EMA layer, GB300 (sm_103a) — round 11
// bf16 mma.sync filter + exact fp32 recheck; prep batched 8 rows/block.
// ---------------------------------------------------------------------------

constexpr int Dc = 256, Kc = 1024, Nrows = 16384, TM = 128;
constexpr float DECAYF = 0.99f, OMDF = 0.01f, EPSF = 1e-5f, KEPSF = 0.01024f;
constexpr float THETA = 8e-3f;     // > 3x hard |bf16 score - exact score| bound
constexpr int CAP = 32;

// ----- smem byte offsets (vq_main) -----
constexpr int SB_XP   = 0;                 // packed A tile (bf16 frags): 64KB
constexpr int SB_WSQ  = 65536;             // 1024 f32 = 4KB
constexpr int SB_RMIN = 69632;             // 128 u32
constexpr int SB_CNT  = 70144;             // 128 i32
constexpr int SB_LIST = 70656;             // 128 x 32 i32 = 16KB
constexpr int SB_FIN  = 87040;             // 128 i32
constexpr int SB_RED  = 87552;             // 8 f32 (+pad)
constexpr int SB_BEST = 87616;             // 128 u64 = 1KB
constexpr int SMEM_MAIN = 88640;

// ----- device scratch (no allocations allowed) -----
__device__ float g_xsq[Nrows];
__device__ float g_wsq[Kc];
__device__ uint2 g_wpb[65536];      // bf16 B fragments
__device__ float g_dw[Kc * Dc];
__device__ float g_counts[Kc];
__device__ float g_loss;
__device__ float g_n;               // 0.99*sum(ema_cs) + 0.01*Nrows

__device__ __forceinline__ uint32_t encf(float x) {
  uint32_t u = __float_as_uint(x);
  return (u & 0x80000000u) ? ~u : (u | 0x80000000u);
}
__device__ __forceinline__ float decf(uint32_t e) {
  return (e & 0x80000000u) ? __uint_as_float(e ^ 0x80000000u) : __uint_as_float(~e);
}
__device__ __forceinline__ uint32_t pkbf(float a, float b) {
  __nv_bfloat162 h = __floats2bfloat162_rn(a, b);
  return *reinterpret_cast<uint32_t*>(&h);
}

// ---------------------------------------------------------------------------
// Kernel 0: xsq/wsq, 8 rows per block with per-row reduction trees that are
// BIT-IDENTICAL to the one-row-per-block version of all passing rounds
// (same lane->value map, same shfl offsets, same ascending red[] chain).
// Extra last block computes g_n with the exact tree emacs used before.
// ---------------------------------------------------------------------------
__global__ void prep_kernel(const float* __restrict__ x, const float* __restrict__ w,
                            const float* __restrict__ ema_cs) {
  const int t = threadIdx.x;
  __shared__ float red[8][8];

  if (blockIdx.x == (Nrows + Kc) / 8) {
    // ---- g_n block: same tree emacs_kernel used (bit-identical S)
    float4 v = reinterpret_cast<const float4*>(ema_cs)[t];
    float s = v.x + v.y + v.z + v.w;
    #pragma unroll
    for (int o = 16; o; o >>= 1) s += __shfl_down_sync(0xffffffffu, s, o);
    if ((t & 31) == 0) red[0][t >> 5] = s;
    __syncthreads();
    if (t == 0) {
      float S = red[0][0];
      #pragma unroll
      for (int i = 1; i < 8; i++) S += red[0][i];
      g_n = DECAYF * S + OMDF * (float)Nrows;
    }
    return;
  }

  const int base = blockIdx.x * 8;
  float v[8];
  // preload (MLP=8); w-row side effects done inline (stores don't block)
  #pragma unroll
  for (int j = 0; j < 8; j++) {
    int b = base + j;
    if (b < Nrows) {
      v[j] = x[(size_t)b * Dc + t];
    } else {
      int k = b - Nrows;
      float wv = w[(size_t)k * Dc + t];
      v[j] = wv;
      int rem = t & 15;
      size_t e = ((size_t)(k >> 3) * 16 + (t >> 4)) * 32 + (k & 7) * 4 + ((rem & 7) >> 1);
      reinterpret_cast<__nv_bfloat16*>(g_wpb)[e * 4 + (rem >> 3) * 2 + (rem & 1)] =
          __float2bfloat16_rn(wv);
      g_dw[(size_t)k * Dc + t] = 0.0f;
      if (t == 0) g_counts[k] = 0.0f;
      if (t == 1 && k == 0) g_loss = 0.0f;
    }
  }
  // 8 independent, structurally identical trees (ILP hides shfl latency)
  #pragma unroll
  for (int j = 0; j < 8; j++) {
    float s = v[j] * v[j];
    #pragma unroll
    for (int o = 16; o; o >>= 1) s += __shfl_down_sync(0xffffffffu, s, o);
    if ((t & 31) == 0) red[j][t >> 5] = s;
  }
  __syncthreads();
  if (t < 8) {
    float tot = red[t][0];
    #pragma unroll
    for (int i = 1; i < 8; i++) tot += red[t][i];
    int b = base + t;
    if (b < Nrows) g_xsq[b] = tot;
    else           g_wsq[b - Nrows] = tot;
  }
}

// ---------------------------------------------------------------------------
// Kernel 1: bf16 mma.sync GEMM filter + parallel exact recheck + epilogue.
// 128 CTAs x 256 threads (8 warps: 2 row-halves x 4 col-groups).
// ---------------------------------------------------------------------------
__global__ void __launch_bounds__(256, 1)
vq_main(const float* __restrict__ x, const float* __restrict__ w,
        float* __restrict__ outQ) {
  extern __shared__ char smem[];
  uint4* sA4 = reinterpret_cast<uint4*>(smem + SB_XP);
  float*  sWsq = reinterpret_cast<float*>(smem + SB_WSQ);
  uint32_t* sRmin = reinterpret_cast<uint32_t*>(smem + SB_RMIN);
  int* sCnt  = reinterpret_cast<int*>(smem + SB_CNT);
  int* sList = reinterpret_cast<int*>(smem + SB_LIST);
  int* sFin  = reinterpret_cast<int*>(smem + SB_FIN);
  float* sRed = reinterpret_cast<float*>(smem + SB_RED);
  unsigned long long* sBest = reinterpret_cast<unsigned long long*>(smem + SB_BEST);

  const int tid = threadIdx.x;
  const int lane = tid & 31;
  const int wid = tid >> 5;
  const int gid = lane >> 2;
  const int tg  = lane & 3;
  const int rh = wid & 1;
  const int cg = wid >> 1;
  const int rowBase = blockIdx.x * TM;

  if (tid < 128) {
    sRmin[tid] = 0xFFFFFFFFu;
    sCnt[tid] = 0;
    sBest[tid] = 0xFFFFFFFFFFFFFFFFull;
  }
  #pragma unroll
  for (int i = 0; i < 4; i++) sWsq[tid + 256 * i] = g_wsq[tid + 256 * i];

  // ---- pack A (x -> bf16 fragments)
  {
    #pragma unroll
    for (int i = 0; i < 16; i++) {
      int pidx = tid + 256 * i;
      int blk = pidx >> 5;
      int k16 = blk & 15, mblk = blk >> 4;
      int r = mblk * 16 + gid;
      int c0 = k16 * 16 + 2 * tg;
      const float* xb = x + (size_t)(rowBase + r) * Dc + c0;
      float2 v00 = *reinterpret_cast<const float2*>(xb);
      float2 v10 = *reinterpret_cast<const float2*>(xb + 8 * Dc);
      float2 v01 = *reinterpret_cast<const float2*>(xb + 8);
      float2 v11 = *reinterpret_cast<const float2*>(xb + 8 * Dc + 8);
      uint4 o;
      o.x = pkbf(v00.x, v00.y);
      o.y = pkbf(v10.x, v10.y);
      o.z = pkbf(v01.x, v01.y);
      o.w = pkbf(v11.x, v11.y);
      sA4[pidx] = o;
    }
  }
  __syncthreads();

  // ---- GEMM filter: 4 chunks of 64 cols per warp
  for (int ch = 0; ch < 4; ch++) {
    const int cb = cg * 256 + ch * 64;
    const uint2* bbase = g_wpb + (size_t)(cb >> 3) * 512 + lane;

    float c[4][8][4];
    #pragma unroll
    for (int i = 0; i < 4; i++)
      #pragma unroll
      for (int j = 0; j < 8; j++)
        c[i][j][0] = c[i][j][1] = c[i][j][2] = c[i][j][3] = 0.0f;

    uint2 bv[8], bn[8];
    #pragma unroll
    for (int nt = 0; nt < 8; nt++) bv[nt] = bbase[nt * 512];

    #pragma unroll
    for (int k16 = 0; k16 < 16; k16++) {
      if (k16 < 15) {
        #pragma unroll
        for (int nt = 0; nt < 8; nt++) bn[nt] = bbase[nt * 512 + (k16 + 1) * 32];
      }
      uint4 a[4];
      #pragma unroll
      for (int m = 0; m < 4; m++)
        a[m] = sA4[((rh * 4 + m) * 16 + k16) * 32 + lane];
      #pragma unroll
      for (int m = 0; m < 4; m++) {
        #pragma unroll
        for (int nt = 0; nt < 8; nt++) {
          asm volatile(
            "mma.sync.aligned.m16n8k16.row.col.f32.bf16.bf16.f32 "
            "{%0,%1,%2,%3},{%4,%5,%6,%7},{%8,%9},{%0,%1,%2,%3};"
            : "+f"(c[m][nt][0]), "+f"(c[m][nt][1]), "+f"(c[m][nt][2]), "+f"(c[m][nt][3])
            : "r"(a[m].x), "r"(a[m].y), "r"(a[m].z), "r"(a[m].w),
              "r"(bv[nt].x), "r"(bv[nt].y));
        }
      }
      #pragma unroll
      for (int nt = 0; nt < 8; nt++) bv[nt] = bn[nt];
    }

    // ---- phase A: per-row min; quad shfl-reduce then one atomicMin per quad
    #pragma unroll
    for (int m = 0; m < 4; m++) {
      float m0 = 3.4e38f, m1 = 3.4e38f;
      #pragma unroll
      for (int nt = 0; nt < 8; nt++) {
        int col0 = cb + nt * 8 + 2 * tg;
        float s0 = fmaf(-2.0f, c[m][nt][0], sWsq[col0]);
        float s1 = fmaf(-2.0f, c[m][nt][1], sWsq[col0 + 1]);
        float s2 = fmaf(-2.0f, c[m][nt][2], sWsq[col0]);
        float s3 = fmaf(-2.0f, c[m][nt][3], sWsq[col0 + 1]);
        m0 = fminf(m0, fminf(s0, s1));
        m1 = fminf(m1, fminf(s2, s3));
      }
      m0 = fminf(m0, __shfl_xor_sync(0xffffffffu, m0, 1));
      m0 = fminf(m0, __shfl_xor_sync(0xffffffffu, m0, 2));
      m1 = fminf(m1, __shfl_xor_sync(0xffffffffu, m1, 1));
      m1 = fminf(m1, __shfl_xor_sync(0xffffffffu, m1, 2));
      int r0 = (rh * 4 + m) * 16 + gid;
      if (tg == 0) {
        atomicMin(&sRmin[r0], encf(m0));
        atomicMin(&sRmin[r0 + 8], encf(m1));
      }
    }
    __syncthreads();

    // ---- phase B: collect candidates within THETA of (monotone) row min
    #pragma unroll
    for (int m = 0; m < 4; m++) {
      int r0 = (rh * 4 + m) * 16 + gid;
      float th0 = decf(sRmin[r0]) + THETA;
      float th1 = decf(sRmin[r0 + 8]) + THETA;
      #pragma unroll
      for (int nt = 0; nt < 8; nt++) {
        int col0 = cb + nt * 8 + 2 * tg;
        float s0 = fmaf(-2.0f, c[m][nt][0], sWsq[col0]);
        float s1 = fmaf(-2.0f, c[m][nt][1], sWsq[col0 + 1]);
        float s2 = fmaf(-2.0f, c[m][nt][2], sWsq[col0]);
        float s3 = fmaf(-2.0f, c[m][nt][3], sWsq[col0 + 1]);
        if (s0 < th0) { int p = atomicAdd(&sCnt[r0], 1);     if (p < CAP) sList[r0 * CAP + p] = col0; }
        if (s1 < th0) { int p = atomicAdd(&sCnt[r0], 1);     if (p < CAP) sList[r0 * CAP + p] = col0 + 1; }
        if (s2 < th1) { int p = atomicAdd(&sCnt[r0 + 8], 1); if (p < CAP) sList[(r0 + 8) * CAP + p] = col0; }
        if (s3 < th1) { int p = atomicAdd(&sCnt[r0 + 8], 1); if (p < CAP) sList[(r0 + 8) * CAP + p] = col0 + 1; }
      }
    }
    __syncthreads();
  }

  // ---- exact recheck: 2 threads per row, 4-wide independent chains.
  // Per-candidate chain bit-identical to all passing rounds; combine via
  // lexicographic (encf(score), k) u64 min == (score, lowest-k) rule.
  // CAP overflow (statistically never) -> full exact scan of all K.
  {
    int row = tid & 127;
    int h = tid >> 7;
    int ncRaw = sCnt[row];
    bool ovf = (ncRaw > CAP);
    int nc = ovf ? Kc : ncRaw;
    if (!ovf && nc == 1) {
      if (h == 0) sBest[row] = (unsigned long long)(uint32_t)sList[row * CAP];
    } else {
      int mc = (nc - h + 1) >> 1;     // this thread's candidates: h, h+2, ...
      if (mc > 0) {
        float xsq = g_xsq[rowBase + row];
        const float4* xr = reinterpret_cast<const float4*>(x + (size_t)(rowBase + row) * Dc);
        float bs = 3.4e38f; int kb = Kc;
        for (int b = 0; b < mc; b += 4) {
          int kk[4];
          #pragma unroll
          for (int j = 0; j < 4; j++) {
            int idx = b + j;
            int slot = h + 2 * ((idx < mc) ? idx : b);
            kk[j] = ovf ? slot : sList[row * CAP + slot];
          }
          const float4* w0 = reinterpret_cast<const float4*>(w + (size_t)kk[0] * Dc);
          const float4* w1 = reinterpret_cast<const float4*>(w + (size_t)kk[1] * Dc);
          const float4* w2 = reinterpret_cast<const float4*>(w + (size_t)kk[2] * Dc);
          const float4* w3 = reinterpret_cast<const float4*>(w + (size_t)kk[3] * Dc);
          float a0 = 0.f, a1 = 0.f, a2 = 0.f, a3 = 0.f;
          #pragma unroll 4
          for (int d4 = 0; d4 < 64; d4++) {
            float4 xv = xr[d4];
            float4 v0 = w0[d4], v1 = w1[d4], v2 = w2[d4], v3 = w3[d4];
            a0 = fmaf(xv.x, v0.x, a0); a0 = fmaf(xv.y, v0.y, a0);
            a0 = fmaf(xv.z, v0.z, a0); a0 = fmaf(xv.w, v0.w, a0);
            a1 = fmaf(xv.x, v1.x, a1); a1 = fmaf(xv.y, v1.y, a1);
            a1 = fmaf(xv.z, v1.z, a1); a1 = fmaf(xv.w, v1.w, a1);
            a2 = fmaf(xv.x, v2.x, a2); a2 = fmaf(xv.y, v2.y, a2);
            a2 = fmaf(xv.z, v2.z, a2); a2 = fmaf(xv.w, v2.w, a2);
            a3 = fmaf(xv.x, v3.x, a3); a3 = fmaf(xv.y, v3.y, a3);
            a3 = fmaf(xv.z, v3.z, a3); a3 = fmaf(xv.w, v3.w, a3);
          }
          float ac[4] = {a0, a1, a2, a3};
          #pragma unroll
          for (int j = 0; j < 4; j++) {
            if (b + j < mc) {
              float r1 = __fadd_rn(xsq, sWsq[kk[j]]);
              float s  = __fadd_rn(r1, -2.0f * ac[j]);
              if (s < bs || (s == bs && kk[j] < kb)) { bs = s; kb = kk[j]; }
            }
          }
        }
        atomicMin(&sBest[row], ((unsigned long long)encf(bs) << 32) | (uint32_t)kb);
      }
    }
  }
  __syncthreads();
  if (tid < 128) {
    int kbest = (int)(sBest[tid] & 0xFFFFFFFFull);
    sFin[tid] = kbest;
    atomicAdd(&g_counts[kbest], 1.0f);
  }
  __syncthreads();

  // ---- epilogue: gather quantized rows, loss partial, dw scatter (vec atomics)
  float lsum = 0.0f;
  {
    int q = tid & 63, rg = tid >> 6;
    #pragma unroll 4
    for (int it = 0; it < 32; ++it) {
      int row = rg * 32 + it;
      int k = sFin[row];
      float4 wv = *reinterpret_cast<const float4*>(w + (size_t)k * Dc + 4 * q);
      float4 xv = *reinterpret_cast<const float4*>(x + (size_t)(rowBase + row) * Dc + 4 * q);
      *reinterpret_cast<float4*>(outQ + (size_t)(rowBase + row) * Dc + 4 * q) = wv;
      float d0 = xv.x - wv.x, d1 = xv.y - wv.y, d2 = xv.z - wv.z, d3 = xv.w - wv.w;
      lsum += d0 * d0 + d1 * d1 + d2 * d2 + d3 * d3;
      atomicAdd(reinterpret_cast<float4*>(g_dw + (size_t)k * Dc + 4 * q), xv);
    }
  }
  #pragma unroll
  for (int o = 16; o; o >>= 1) lsum += __shfl_down_sync(0xffffffffu, lsum, o);
  if ((tid & 31) == 0) sRed[tid >> 5] = lsum;
  __syncthreads();
  if (tid == 0) {
    float tot = sRed[0];
    #pragma unroll
    for (int i = 1; i < 8; i++) tot += sRed[i];
    atomicAdd(&g_loss, tot);
  }
}

// ---------------------------------------------------------------------------
// Kernel 2: cluster-size EMA + Laplace + ema_w EMA + embed.
// n comes precomputed from prep (g_n) -> no per-block reduction.
// ---------------------------------------------------------------------------
__global__ void emacs_kernel(const float* __restrict__ ema_cs,
                             const float* __restrict__ ema_w,
                             float* __restrict__ outLoss, float* __restrict__ outEmbed,
                             float* __restrict__ outCS, float* __restrict__ outEmaW) {
  int k = blockIdx.x, d = threadIdx.x;
  __shared__ float s_cs;
  if (d == 0) {
    float n = g_n;
    float c = ema_cs[k] * DECAYF + OMDF * g_counts[k];
    float csf = (c + EPSF) / (n + KEPSF) * n;
    s_cs = csf;
    outCS[k] = csf;
    if (k == 0) outLoss[0] = 0.25f * g_loss * (1.0f / 4194304.0f);
  }
  __syncthreads();
  size_t i = (size_t)k * Dc + d;
  float ew = ema_w[i] * DECAYF + OMDF * g_dw[i];
  outEmaW[i]  = ew;
  outEmbed[i] = ew / s_cs;
}

// ---------------------------------------------------------------------------
extern "C" void kernel_launch(void* const* d_in, const int* in_sizes, int n_in,
                              void* d_out, int out_size) {
  const float* x      = (const float*)d_in[0];
  const float* w      = (const float*)d_in[1];
  const float* ema_cs = (const float*)d_in[2];
  const float* ema_w  = (const float*)d_in[3];

  float* out      = (float*)d_out;
  float* outQ     = out;
  float* outLoss  = out + (size_t)Nrows * Dc;
  float* outEmbed = outLoss + 1;
  float* outCS    = outEmbed + (size_t)Kc * Dc;
  float* outEmaW  = outCS + Kc;

  cudaFuncSetAttribute(vq_main, cudaFuncAttributeMaxDynamicSharedMemorySize, SMEM_MAIN);

  prep_kernel<<<(Nrows + Kc) / 8 + 1, 256>>>(x, w, ema_cs);
  vq_main<<<Nrows / TM, 256, SMEM_MAIN>>>(x, w, outQ);
  emacs_kernel<<<Kc, 256>>>(ema_cs, ema_w, outLoss, outEmbed, outCS, outEmaW);
}